// round 2
// baseline (speedup 1.0000x reference)
#include <cuda_runtime.h>

#define NBLK 128
#define NTHR 256
#define B 256
#define TE 300
#define TT 600
#define H 512
#define NIN 128
#define NPV 5
#define EMBD 32
#define NHE 16

// ---------------- scratch (device globals; no allocation) ----------------
__device__ float g_h0[B * H];          // enc L0 hidden -> decoder d1
__device__ float g_h1[B * H];          // enc L1 hidden -> decoder d2
__device__ float g_gates[B * 3072];    // [B][ gi(1536) | gh(1536) ]
__device__ float g_z[B * 256];         // heads intermediate (relu'd): fc1(128) | he1(128)
__device__ float g_pv[B * NPV];        // recurrent pv
__device__ float g_embs[B * EMBD];     // emb[scenario[b]]
__device__ unsigned g_bar_count;
__device__ unsigned g_bar_sense;

// ---------------- grid-wide barrier (all 128 CTAs co-resident) ----------------
__device__ __forceinline__ void gsync(unsigned& sense) {
    __syncthreads();
    if (threadIdx.x == 0) {
        __threadfence();
        unsigned prev = atomicAdd(&g_bar_count, 1u);
        if (prev == (unsigned)(NBLK - 1)) {
            atomicExch(&g_bar_count, 0u);
            __threadfence();
            *((volatile unsigned*)&g_bar_sense) = sense ^ 1u;
        } else {
            while (*((volatile unsigned*)&g_bar_sense) == sense) __nanosleep(32);
            __threadfence();
        }
    }
    sense ^= 1u;
    __syncthreads();
}

// ---------------- A-matrix loaders for the gi region ----------------
// MODE 0: encoder L0 input  = concat(x_cv[:,t,:], emb_s)            Kin=160
// MODE 1: plain matrix      = x[b*ldx + k]                          Kin=512
// MODE 2: decoder L0 input  = concat(x_cv_target[:,t,:], pv, pad)   Kin=133 padded to 160
template <int MODE>
__device__ __forceinline__ float loadA_gi(const float* __restrict__ x, int ldx,
                                          const float* __restrict__ pv, int b, int k) {
    if (MODE == 0) {
        return (k < NIN) ? x[b * ldx + k] : g_embs[b * EMBD + (k - NIN)];
    } else if (MODE == 1) {
        return x[b * ldx + k];
    } else {
        if (k < NIN) return x[b * ldx + k];
        if (k < NIN + NPV) return pv[b * NPV + (k - NIN)];
        return 0.f;
    }
}

// ---------------- fused gates GEMM: gi = A_in @ Wih^T + bih ; gh = h @ Whh^T + bhh ----------------
// Output 256 x 3072 into g_gates. Tiles: 4 (M=64) x 32 (N=96, 16 gi + 16 gh) = 128 = grid.
template <int MODE>
__device__ __forceinline__ void phase_gates(
    const float* __restrict__ xb, int ldx,
    const float* __restrict__ pv,
    const float* __restrict__ Wih, int ldWih, int Kpad,
    const float* __restrict__ bih,
    const float* __restrict__ hbuf,
    const float* __restrict__ Whh,
    const float* __restrict__ bhh) {
    __shared__ float As[64 * 33];
    __shared__ float Ws[96 * 33];

    int tile = blockIdx.x;
    int mt = tile >> 5;
    int ct = tile & 31;
    int m0 = mt * 64;
    bool is_gh = (ct >= 16);
    int j0 = (is_gh ? (ct - 16) : ct) * 96;
    const float* W = is_gh ? Whh : Wih;
    int ldw = is_gh ? H : ldWih;
    const float* bias = is_gh ? bhh : bih;
    int K = is_gh ? H : Kpad;

    int tid = threadIdx.x;
    int tm4 = (tid >> 4) * 4;   // 0..60
    int tn6 = (tid & 15) * 6;   // 0..90

    float acc[4][6];
#pragma unroll
    for (int r = 0; r < 4; r++)
#pragma unroll
        for (int c = 0; c < 6; c++) acc[r][c] = 0.f;

    for (int kb = 0; kb < K; kb += 32) {
        // stage A tile: 64 rows x 32 k  (coalesced along k)
#pragma unroll
        for (int i = 0; i < 8; i++) {
            int lin = tid + i * NTHR;
            int kk = lin & 31, mm = lin >> 5;
            int b = m0 + mm, k = kb + kk;
            float v;
            if (is_gh) v = hbuf[b * H + k];
            else       v = loadA_gi<MODE>(xb, ldx, pv, b, k);
            As[mm * 33 + kk] = v;
        }
        // stage W tile: 96 rows x 32 k  (zero-pad k >= ldw, e.g. dec_Wih0 ldw=133)
#pragma unroll
        for (int i = 0; i < 12; i++) {
            int lin = tid + i * NTHR;
            int kk = lin & 31, jj = lin >> 5;
            int k = kb + kk;
            Ws[jj * 33 + kk] = (k < ldw) ? W[(j0 + jj) * ldw + k] : 0.f;
        }
        __syncthreads();
#pragma unroll
        for (int k = 0; k < 32; k++) {
            float a[4], w[6];
#pragma unroll
            for (int r = 0; r < 4; r++) a[r] = As[(tm4 + r) * 33 + k];
#pragma unroll
            for (int c = 0; c < 6; c++) w[c] = Ws[(tn6 + c) * 33 + k];
#pragma unroll
            for (int r = 0; r < 4; r++)
#pragma unroll
                for (int c = 0; c < 6; c++) acc[r][c] += a[r] * w[c];
        }
        __syncthreads();
    }

    int base = is_gh ? 1536 : 0;
#pragma unroll
    for (int r = 0; r < 4; r++) {
        int b = m0 + tm4 + r;
#pragma unroll
        for (int c = 0; c < 6; c++) {
            int j = j0 + tn6 + c;
            g_gates[b * 3072 + base + j] = acc[r][c] + bias[j];
        }
    }
}

__device__ __forceinline__ float sigf(float x) { return 1.f / (1.f + __expf(-x)); }

// ---------------- GRU elementwise combine: h <- (1-z)*n + z*h ----------------
__device__ __forceinline__ void phase_combine(float* __restrict__ h) {
    int gt = blockIdx.x * NTHR + threadIdx.x;
    int e0 = gt * 4;                 // 128*256*4 = 131072 = B*H exactly
    int b = e0 >> 9;
    int j = e0 & 511;
    const float* gb = g_gates + b * 3072 + j;
    float4 ir = *(const float4*)(gb);
    float4 iz = *(const float4*)(gb + 512);
    float4 in_ = *(const float4*)(gb + 1024);
    float4 hr = *(const float4*)(gb + 1536);
    float4 hz = *(const float4*)(gb + 2048);
    float4 hn = *(const float4*)(gb + 2560);
    float4 hv = *(float4*)(h + b * H + j);

    float rr, zz, nn;
    rr = sigf(ir.x + hr.x); zz = sigf(iz.x + hz.x); nn = tanhf(in_.x + rr * hn.x);
    hv.x = (1.f - zz) * nn + zz * hv.x;
    rr = sigf(ir.y + hr.y); zz = sigf(iz.y + hz.y); nn = tanhf(in_.y + rr * hn.y);
    hv.y = (1.f - zz) * nn + zz * hv.y;
    rr = sigf(ir.z + hr.z); zz = sigf(iz.z + hz.z); nn = tanhf(in_.z + rr * hn.z);
    hv.z = (1.f - zz) * nn + zz * hv.z;
    rr = sigf(ir.w + hr.w); zz = sigf(iz.w + hz.w); nn = tanhf(in_.w + rr * hn.w);
    hv.w = (1.f - zz) * nn + zz * hv.w;

    *(float4*)(h + b * H + j) = hv;
}

// ---------------- heads layer 1: z = relu(d2 @ [fc1|he1]^T + b), 256x256, K=512 ----------------
__device__ __forceinline__ void phase_heads1(const float* __restrict__ fc1W,
                                             const float* __restrict__ fc1b,
                                             const float* __restrict__ he1W,
                                             const float* __restrict__ he1b) {
    __shared__ float As2[32 * 17];   // [k][m], m-tile 16
    __shared__ float Ws2[32 * 34];   // [k][n], n-tile 32 (stride 34 keeps float2 aligned)
    int tile = blockIdx.x;           // 16 m-tiles x 8 n-tiles = 128
    int m0 = (tile >> 3) * 16;
    int n0 = (tile & 7) * 32;
    int tid = threadIdx.x;
    int m = tid & 15;
    int n2 = (tid >> 4) * 2;

    float acc0 = 0.f, acc1 = 0.f;
    for (int kb = 0; kb < H; kb += 32) {
#pragma unroll
        for (int i = 0; i < 2; i++) {
            int lin = tid + i * NTHR;
            int kk = lin & 31, mm = lin >> 5;
            As2[kk * 17 + mm] = g_h1[(m0 + mm) * H + kb + kk];
        }
#pragma unroll
        for (int i = 0; i < 4; i++) {
            int lin = tid + i * NTHR;
            int kk = lin & 31, nn = lin >> 5;
            int ng = n0 + nn;
            const float* Wr = (ng < 128) ? (fc1W + ng * H) : (he1W + (ng - 128) * H);
            Ws2[kk * 34 + nn] = Wr[kb + kk];
        }
        __syncthreads();
#pragma unroll
        for (int k = 0; k < 32; k++) {
            float a = As2[k * 17 + m];
            float2 w = *(const float2*)&Ws2[k * 34 + n2];
            acc0 += a * w.x;
            acc1 += a * w.y;
        }
        __syncthreads();
    }
    int b = m0 + m;
    int ng0 = n0 + n2;
    float b0 = (ng0 < 128) ? fc1b[ng0] : he1b[ng0 - 128];
    float b1 = (ng0 + 1 < 128) ? fc1b[ng0 + 1] : he1b[ng0 + 1 - 128];
    g_z[b * 256 + ng0]     = fmaxf(acc0 + b0, 0.f);
    g_z[b * 256 + ng0 + 1] = fmaxf(acc1 + b1, 0.f);
}

// ---------------- heads layer 2: pv (B x 5), he (B x 16); write outputs + recurrent pv ----------------
__device__ __forceinline__ void phase_heads2(int t,
                                             const float* __restrict__ fc2W,
                                             const float* __restrict__ fc2b,
                                             const float* __restrict__ he2W,
                                             const float* __restrict__ he2b,
                                             float* __restrict__ out) {
    __shared__ float zs[512];
    int tid = threadIdx.x;
    int b0 = blockIdx.x * 2;    // 128 CTAs x 2 rows = 256
    for (int i = tid; i < 512; i += NTHR) zs[i] = g_z[b0 * 256 + i];
    __syncthreads();
    int warp = tid >> 5, lane = tid & 31;
    for (int d = warp; d < 42; d += 8) {
        int bb = d / 21, o = d % 21;
        const float* wrow;
        int kbase;
        float bias;
        if (o < 5) { wrow = fc2W + o * 128; kbase = 0; bias = fc2b[o]; }
        else       { wrow = he2W + (o - 5) * 128; kbase = 128; bias = he2b[o - 5]; }
        float s = 0.f;
#pragma unroll
        for (int kk = 0; kk < 128; kk += 32)
            s += zs[bb * 256 + kbase + kk + lane] * wrow[kk + lane];
#pragma unroll
        for (int off = 16; off; off >>= 1) s += __shfl_xor_sync(0xffffffffu, s, off);
        if (lane == 0) {
            float v = s + bias;
            int b = b0 + bb;
            if (o < 5) {
                out[b * (TT * NPV) + t * NPV + o] = v;
                g_pv[b * NPV + o] = v;
            } else {
                out[B * TT * NPV + b * (TT * NHE) + t * NHE + (o - 5)] = v;
            }
        }
    }
}

// ---------------- top-level persistent kernel ----------------
struct P {
    const float *x_cv, *x_cv_target, *pv_init;
    const int* scenario;
    const float* emb;
    const float *eW0i, *eW0h, *eb0i, *eb0h, *eW1i, *eW1h, *eb1i, *eb1h;
    const float *dW0i, *dW0h, *db0i, *db0h, *dW1i, *dW1h, *db1i, *db1h;
    const float *fc1W, *fc1b, *fc2W, *fc2b, *he1W, *he1b, *he2W, *he2b;
    float* out;
};

__global__ void __launch_bounds__(NTHR, 1) gru_kernel(P p) {
    unsigned sense = *((volatile unsigned*)&g_bar_sense);
    int gt = blockIdx.x * NTHR + threadIdx.x;

    // init: zero hiddens, gather scenario embeddings
    for (int i = gt; i < B * H; i += NBLK * NTHR) { g_h0[i] = 0.f; g_h1[i] = 0.f; }
    for (int i = gt; i < B * EMBD; i += NBLK * NTHR) {
        int b = i >> 5;
        g_embs[i] = p.emb[p.scenario[b] * EMBD + (i & 31)];
    }
    gsync(sense);

    // ---------------- encoder: both layers interleaved per timestep ----------------
    for (int t = 0; t < TE; t++) {
        phase_gates<0>(p.x_cv + t * NIN, TE * NIN, nullptr,
                       p.eW0i, 160, 160, p.eb0i, g_h0, p.eW0h, p.eb0h);
        gsync(sense);
        phase_combine(g_h0);
        gsync(sense);
        phase_gates<1>(g_h0, H, nullptr,
                       p.eW1i, H, H, p.eb1i, g_h1, p.eW1h, p.eb1h);
        gsync(sense);
        phase_combine(g_h1);
        gsync(sense);
    }

    // ---------------- autoregressive decoder ----------------
    for (int t = 0; t < TT; t++) {
        const float* pv = (t == 0) ? p.pv_init : g_pv;
        phase_gates<2>(p.x_cv_target + t * NIN, TT * NIN, pv,
                       p.dW0i, 133, 160, p.db0i, g_h0, p.dW0h, p.db0h);
        gsync(sense);
        phase_combine(g_h0);     // d1
        gsync(sense);
        phase_gates<1>(g_h0, H, nullptr,
                       p.dW1i, H, H, p.db1i, g_h1, p.dW1h, p.db1h);
        gsync(sense);
        phase_combine(g_h1);     // d2
        gsync(sense);
        phase_heads1(p.fc1W, p.fc1b, p.he1W, p.he1b);
        gsync(sense);
        phase_heads2(t, p.fc2W, p.fc2b, p.he2W, p.he2b, p.out);
        gsync(sense);
    }
}

extern "C" void kernel_launch(void* const* d_in, const int* in_sizes, int n_in,
                              void* d_out, int out_size) {
    (void)in_sizes; (void)n_in; (void)out_size;
    P p;
    p.x_cv        = (const float*)d_in[0];
    p.x_cv_target = (const float*)d_in[1];
    p.pv_init     = (const float*)d_in[2];
    p.scenario    = (const int*)d_in[3];
    p.emb         = (const float*)d_in[4];
    p.eW0i = (const float*)d_in[5];  p.eW0h = (const float*)d_in[6];
    p.eb0i = (const float*)d_in[7];  p.eb0h = (const float*)d_in[8];
    p.eW1i = (const float*)d_in[9];  p.eW1h = (const float*)d_in[10];
    p.eb1i = (const float*)d_in[11]; p.eb1h = (const float*)d_in[12];
    p.dW0i = (const float*)d_in[13]; p.dW0h = (const float*)d_in[14];
    p.db0i = (const float*)d_in[15]; p.db0h = (const float*)d_in[16];
    p.dW1i = (const float*)d_in[17]; p.dW1h = (const float*)d_in[18];
    p.db1i = (const float*)d_in[19]; p.db1h = (const float*)d_in[20];
    p.fc1W = (const float*)d_in[21]; p.fc1b = (const float*)d_in[22];
    p.fc2W = (const float*)d_in[23]; p.fc2b = (const float*)d_in[24];
    p.he1W = (const float*)d_in[25]; p.he1b = (const float*)d_in[26];
    p.he2W = (const float*)d_in[27]; p.he2b = (const float*)d_in[28];
    p.out  = (float*)d_out;
    gru_kernel<<<NBLK, NTHR>>>(p);
}

// round 3
// speedup vs baseline: 1.1015x; 1.1015x over previous
#include <cuda_runtime.h>

#define NBLK 128
#define NTHR 256
#define B 256
#define TE 300
#define TT 600
#define H 512
#define NIN 128
#define NPV 5
#define EMBD 32
#define NHE 16

typedef unsigned long long ull;

__device__ float g_h0a[B * H], g_h0b[B * H];
__device__ float g_h1a[B * H], g_h1b[B * H];
__device__ float g_z[B * 256];
__device__ float g_pv[B * NPV];
__device__ float g_embs[B * EMBD];
__device__ unsigned g_bar_count;
__device__ unsigned g_bar_sense;

__device__ __forceinline__ void gsync(unsigned& sense) {
    __syncthreads();
    if (threadIdx.x == 0) {
        __threadfence();
        unsigned prev = atomicAdd(&g_bar_count, 1u);
        if (prev == (unsigned)(NBLK - 1)) {
            atomicExch(&g_bar_count, 0u);
            __threadfence();
            *((volatile unsigned*)&g_bar_sense) = sense ^ 1u;
        } else {
            while (*((volatile unsigned*)&g_bar_sense) == sense) __nanosleep(32);
            __threadfence();
        }
    }
    sense ^= 1u;
    __syncthreads();
}

__device__ __forceinline__ void fma2(ull& a, ull x, ull w) {
    asm("fma.rn.f32x2 %0, %1, %2, %0;" : "+l"(a) : "l"(x), "l"(w));
}
__device__ __forceinline__ ull dup2(float w) {
    ull r; unsigned u = __float_as_uint(w);
    asm("mov.b64 %0, {%1,%1};" : "=l"(r) : "r"(u));
    return r;
}
__device__ __forceinline__ float2 u2f(ull v) {
    unsigned lo, hi;
    asm("mov.b64 {%0,%1}, %2;" : "=r"(lo), "=r"(hi) : "l"(v));
    float2 r; r.x = __uint_as_float(lo); r.y = __uint_as_float(hi);
    return r;
}
__device__ __forceinline__ float sigf(float x) { return 1.f / (1.f + __expf(-x)); }

// 3-gate sub-GEMM for a 64(m) x 16(j) x 3(gate) tile. acc = packed f32x2 over m-pairs.
// AMODE: 0 plain rows (stride ldA), 1 concat x(128)+embs(32). WMODE: 0 float4 loads, 1 scalar (ld=133).
template <int AMODE, int WMODE>
__device__ __forceinline__ void gemm3(
    const float* __restrict__ A, int ldA,
    const float* __restrict__ W, int ldW, int K,
    int m0, int j0, int tm, int tn,
    float* __restrict__ sA, ull* __restrict__ sW, ull (&acc)[2][3]) {
    const int tid = threadIdx.x;
    const int NC = K >> 5;
    float4 pA[2]; float4 pW4[2]; float pWs[6];

    auto ld = [&](int kb) {
#pragma unroll
        for (int i = 0; i < 2; i++) {
            int f = tid + (i << 8);
            int mm = f >> 3, kq = f & 7, k = kb + (kq << 2);
            if (AMODE == 1 && k >= 128)
                pA[i] = *(const float4*)&g_embs[(m0 + mm) * EMBD + (k - 128)];
            else
                pA[i] = *(const float4*)&A[(m0 + mm) * ldA + k];
        }
        if (WMODE == 0) {
#pragma unroll
            for (int i = 0; i < 2; i++) {
                int f = tid + (i << 8);
                if (f < 384) {
                    int wr = f >> 3, kq = f & 7;
                    int grow = ((wr >> 4) << 9) + j0 + (wr & 15);
                    pW4[i] = *(const float4*)&W[grow * ldW + kb + (kq << 2)];
                }
            }
        } else {
#pragma unroll
            for (int i = 0; i < 6; i++) {
                int f = tid + (i << 8);
                int wr = f >> 5, kk = f & 31;
                int grow = ((wr >> 4) << 9) + j0 + (wr & 15);
                pWs[i] = W[grow * ldW + kb + kk];
            }
        }
    };
    auto st = [&]() {
#pragma unroll
        for (int i = 0; i < 2; i++) {
            int f = tid + (i << 8);
            int mm = f >> 3, kq = f & 7;
            sA[((kq << 2) + 0) * 68 + mm] = pA[i].x;
            sA[((kq << 2) + 1) * 68 + mm] = pA[i].y;
            sA[((kq << 2) + 2) * 68 + mm] = pA[i].z;
            sA[((kq << 2) + 3) * 68 + mm] = pA[i].w;
        }
        if (WMODE == 0) {
#pragma unroll
            for (int i = 0; i < 2; i++) {
                int f = tid + (i << 8);
                if (f < 384) {
                    int wr = f >> 3, kq = f & 7;
                    sW[((kq << 2) + 0) * 49 + wr] = dup2(pW4[i].x);
                    sW[((kq << 2) + 1) * 49 + wr] = dup2(pW4[i].y);
                    sW[((kq << 2) + 2) * 49 + wr] = dup2(pW4[i].z);
                    sW[((kq << 2) + 3) * 49 + wr] = dup2(pW4[i].w);
                }
            }
        } else {
#pragma unroll
            for (int i = 0; i < 6; i++) {
                int f = tid + (i << 8);
                int wr = f >> 5, kk = f & 31;
                sW[kk * 49 + wr] = dup2(pWs[i]);
            }
        }
    };

    ld(0);
    for (int c = 0; c < NC; c++) {
        st();
        __syncthreads();
        if (c + 1 < NC) ld((c + 1) << 5);
#pragma unroll
        for (int k = 0; k < 32; k++) {
            ulonglong2 av = *(const ulonglong2*)&sA[k * 68 + (tm << 2)];
            ull w0 = sW[k * 49 + tn];
            ull w1 = sW[k * 49 + 16 + tn];
            ull w2 = sW[k * 49 + 32 + tn];
            fma2(acc[0][0], av.x, w0); fma2(acc[1][0], av.y, w0);
            fma2(acc[0][1], av.x, w1); fma2(acc[1][1], av.y, w1);
            fma2(acc[0][2], av.x, w2); fma2(acc[1][2], av.y, w2);
        }
        __syncthreads();
    }
}

template <bool PV>
__device__ __forceinline__ void combine3(
    ull (&aI)[2][3], ull (&aH)[2][3],
    const float* __restrict__ bias, const float* __restrict__ pvw,
    const float* __restrict__ hin, float* __restrict__ hout,
    int m0, int j0, int tm, int tn) {
    int j = j0 + tn;
    float bi0 = bias[tn], bi1 = bias[16 + tn], bi2 = bias[32 + tn];
    float bh0 = bias[48 + tn], bh1 = bias[64 + tn], bh2 = bias[80 + tn];
#pragma unroll
    for (int p = 0; p < 2; p++) {
        float2 vir = u2f(aI[p][0]), viz = u2f(aI[p][1]), vin = u2f(aI[p][2]);
        float2 vhr = u2f(aH[p][0]), vhz = u2f(aH[p][1]), vhn = u2f(aH[p][2]);
#pragma unroll
        for (int u = 0; u < 2; u++) {
            int b = m0 + (tm << 2) + (p << 1) + u;
            float ir = (u ? vir.y : vir.x) + bi0;
            float iz = (u ? viz.y : viz.x) + bi1;
            float in_ = (u ? vin.y : vin.x) + bi2;
            if (PV) {
                const float* pv = &g_pv[b * NPV];
#pragma unroll
                for (int q = 0; q < 5; q++) {
                    float pq = pv[q];
                    ir  += pq * pvw[tn * 5 + q];
                    iz  += pq * pvw[80 + tn * 5 + q];
                    in_ += pq * pvw[160 + tn * 5 + q];
                }
            }
            float hr = (u ? vhr.y : vhr.x) + bh0;
            float hz = (u ? vhz.y : vhz.x) + bh1;
            float hn = (u ? vhn.y : vhn.x) + bh2;
            float r = sigf(ir + hr);
            float z = sigf(iz + hz);
            float n = tanhf(in_ + r * hn);
            hout[b * H + j] = (1.f - z) * n + z * hin[b * H + j];
        }
    }
}

template <int AMODE, int WMODE, bool PV>
__device__ __forceinline__ void gru_step(
    const float* __restrict__ Ain, int ldA,
    const float* __restrict__ Wih, int ldWih, int Kin,
    const float* __restrict__ hin, const float* __restrict__ Whh,
    const float* __restrict__ bias, const float* __restrict__ pvw,
    float* __restrict__ hout,
    int m0, int j0, int tm, int tn, float* sA, ull* sW) {
    ull aI[2][3] = {{0, 0, 0}, {0, 0, 0}};
    ull aH[2][3] = {{0, 0, 0}, {0, 0, 0}};
    gemm3<AMODE, WMODE>(Ain, ldA, Wih, ldWih, Kin, m0, j0, tm, tn, sA, sW, aI);
    gemm3<0, 0>(hin, H, Whh, H, H, m0, j0, tm, tn, sA, sW, aH);
    combine3<PV>(aI, aH, bias, pvw, hin, hout, m0, j0, tm, tn);
}

// heads layer 1: z = relu(d2 @ [fc1|he1]^T + b), 256x256, K=512
__device__ __forceinline__ void heads1(const float* __restrict__ d2,
                                       const float* __restrict__ fc1W, const float* __restrict__ fc1b,
                                       const float* __restrict__ he1W, const float* __restrict__ he1b) {
    __shared__ float As2[32 * 17];
    __shared__ float Ws2[32 * 34];
    int tile = blockIdx.x;
    int m0 = (tile >> 3) * 16;
    int n0 = (tile & 7) * 32;
    int tid = threadIdx.x;
    int m = tid & 15;
    int n2 = (tid >> 4) * 2;

    float acc0 = 0.f, acc1 = 0.f;
    for (int kb = 0; kb < H; kb += 32) {
#pragma unroll
        for (int i = 0; i < 2; i++) {
            int lin = tid + i * NTHR;
            int kk = lin & 31, mm = lin >> 5;
            As2[kk * 17 + mm] = d2[(m0 + mm) * H + kb + kk];
        }
#pragma unroll
        for (int i = 0; i < 4; i++) {
            int lin = tid + i * NTHR;
            int kk = lin & 31, nn = lin >> 5;
            int ng = n0 + nn;
            const float* Wr = (ng < 128) ? (fc1W + ng * H) : (he1W + (ng - 128) * H);
            Ws2[kk * 34 + nn] = Wr[kb + kk];
        }
        __syncthreads();
#pragma unroll
        for (int k = 0; k < 32; k++) {
            float a = As2[k * 17 + m];
            float2 w = *(const float2*)&Ws2[k * 34 + n2];
            acc0 += a * w.x;
            acc1 += a * w.y;
        }
        __syncthreads();
    }
    int b = m0 + m;
    int ng0 = n0 + n2;
    float b0 = (ng0 < 128) ? fc1b[ng0] : he1b[ng0 - 128];
    float b1 = (ng0 + 1 < 128) ? fc1b[ng0 + 1] : he1b[ng0 + 1 - 128];
    g_z[b * 256 + ng0]     = fmaxf(acc0 + b0, 0.f);
    g_z[b * 256 + ng0 + 1] = fmaxf(acc1 + b1, 0.f);
}

__device__ __forceinline__ void heads2(int t,
                                       const float* __restrict__ fc2W, const float* __restrict__ fc2b,
                                       const float* __restrict__ he2W, const float* __restrict__ he2b,
                                       float* __restrict__ out) {
    __shared__ float zs[512];
    int tid = threadIdx.x;
    int b0 = blockIdx.x * 2;
    for (int i = tid; i < 512; i += NTHR) zs[i] = g_z[b0 * 256 + i];
    __syncthreads();
    int warp = tid >> 5, lane = tid & 31;
    for (int d = warp; d < 42; d += 8) {
        int bb = d / 21, o = d % 21;
        const float* wrow;
        int kbase;
        float bias;
        if (o < 5) { wrow = fc2W + o * 128; kbase = 0; bias = fc2b[o]; }
        else       { wrow = he2W + (o - 5) * 128; kbase = 128; bias = he2b[o - 5]; }
        float s = 0.f;
#pragma unroll
        for (int kk = 0; kk < 128; kk += 32)
            s += zs[bb * 256 + kbase + kk + lane] * wrow[kk + lane];
#pragma unroll
        for (int off = 16; off; off >>= 1) s += __shfl_xor_sync(0xffffffffu, s, off);
        if (lane == 0) {
            float v = s + bias;
            int b = b0 + bb;
            if (o < 5) {
                out[b * (TT * NPV) + t * NPV + o] = v;
                g_pv[b * NPV + o] = v;
            } else {
                out[B * TT * NPV + b * (TT * NHE) + t * NHE + (o - 5)] = v;
            }
        }
    }
    __syncthreads();
}

struct P {
    const float *x_cv, *x_cv_target, *pv_init;
    const int* scenario;
    const float* emb;
    const float *eW0i, *eW0h, *eb0i, *eb0h, *eW1i, *eW1h, *eb1i, *eb1h;
    const float *dW0i, *dW0h, *db0i, *db0h, *dW1i, *dW1h, *db1i, *db1h;
    const float *fc1W, *fc1b, *fc2W, *fc2b, *he1W, *he1b, *he2W, *he2b;
    float* out;
};

__global__ void __launch_bounds__(NTHR, 1) gru_kernel(P p) {
    __shared__ __align__(16) float sA[32 * 68];
    __shared__ ull sW[32 * 49];
    __shared__ float sBias[4 * 96];
    __shared__ float sPvw[240];

    unsigned sense = *((volatile unsigned*)&g_bar_sense);
    int tid = threadIdx.x;
    int mt = blockIdx.x >> 5, jt = blockIdx.x & 31;
    int m0 = mt << 6, j0 = jt << 4;
    int tm = tid >> 4, tn = tid & 15;
    int gt = blockIdx.x * NTHR + tid;

    for (int i = gt; i < B * H; i += NBLK * NTHR) { g_h0a[i] = 0.f; g_h1a[i] = 0.f; }
    for (int i = gt; i < B * EMBD; i += NBLK * NTHR)
        g_embs[i] = p.emb[p.scenario[i >> 5] * EMBD + (i & 31)];
    for (int i = gt; i < B * NPV; i += NBLK * NTHR) g_pv[i] = p.pv_init[i];

    {
        const float* bI[4] = { p.eb0i, p.eb1i, p.db0i, p.db1i };
        const float* bH[4] = { p.eb0h, p.eb1h, p.db0h, p.db1h };
        for (int idx = tid; idx < 384; idx += NTHR) {
            int ph = idx / 96, r = idx % 96, g = r >> 4, jj = r & 15;
            sBias[idx] = (g < 3) ? bI[ph][(g << 9) + j0 + jj]
                                 : bH[ph][((g - 3) << 9) + j0 + jj];
        }
        for (int idx = tid; idx < 240; idx += NTHR) {
            int g = idx / 80, r = idx % 80, jj = r / 5, q = r % 5;
            sPvw[idx] = p.dW0i[((g << 9) + j0 + jj) * 133 + 128 + q];
        }
    }
    gsync(sense);

    float* h0buf[2] = { g_h0a, g_h0b };
    float* h1buf[2] = { g_h1a, g_h1b };

    // encoder: 1 grid barrier per step (ping-pong makes the rest race-free)
    for (int t = 0; t < TE; t++) {
        int rd = t & 1, wr = rd ^ 1;
        gru_step<1, 0, false>(p.x_cv + t * NIN, TE * NIN, p.eW0i, 160, 160,
                              h0buf[rd], p.eW0h, sBias, nullptr,
                              h0buf[wr], m0, j0, tm, tn, sA, sW);
        gsync(sense);
        gru_step<0, 0, false>(h0buf[wr], H, p.eW1i, 512, 512,
                              h1buf[rd], p.eW1h, sBias + 96, nullptr,
                              h1buf[wr], m0, j0, tm, tn, sA, sW);
    }

    // decoder
    for (int t = 0; t < TT; t++) {
        int rd = t & 1, wr = rd ^ 1;
        gru_step<0, 1, true>(p.x_cv_target + t * NIN, TT * NIN, p.dW0i, 133, 128,
                             h0buf[rd], p.dW0h, sBias + 192, sPvw,
                             h0buf[wr], m0, j0, tm, tn, sA, sW);
        gsync(sense);
        gru_step<0, 0, false>(h0buf[wr], H, p.dW1i, 512, 512,
                              h1buf[rd], p.dW1h, sBias + 288, nullptr,
                              h1buf[wr], m0, j0, tm, tn, sA, sW);
        gsync(sense);
        heads1(h1buf[wr], p.fc1W, p.fc1b, p.he1W, p.he1b);
        gsync(sense);
        heads2(t, p.fc2W, p.fc2b, p.he2W, p.he2b, p.out);
        gsync(sense);
    }
}

extern "C" void kernel_launch(void* const* d_in, const int* in_sizes, int n_in,
                              void* d_out, int out_size) {
    (void)in_sizes; (void)n_in; (void)out_size;
    P p;
    p.x_cv        = (const float*)d_in[0];
    p.x_cv_target = (const float*)d_in[1];
    p.pv_init     = (const float*)d_in[2];
    p.scenario    = (const int*)d_in[3];
    p.emb         = (const float*)d_in[4];
    p.eW0i = (const float*)d_in[5];  p.eW0h = (const float*)d_in[6];
    p.eb0i = (const float*)d_in[7];  p.eb0h = (const float*)d_in[8];
    p.eW1i = (const float*)d_in[9];  p.eW1h = (const float*)d_in[10];
    p.eb1i = (const float*)d_in[11]; p.eb1h = (const float*)d_in[12];
    p.dW0i = (const float*)d_in[13]; p.dW0h = (const float*)d_in[14];
    p.db0i = (const float*)d_in[15]; p.db0h = (const float*)d_in[16];
    p.dW1i = (const float*)d_in[17]; p.dW1h = (const float*)d_in[18];
    p.db1i = (const float*)d_in[19]; p.db1h = (const float*)d_in[20];
    p.fc1W = (const float*)d_in[21]; p.fc1b = (const float*)d_in[22];
    p.fc2W = (const float*)d_in[23]; p.fc2b = (const float*)d_in[24];
    p.he1W = (const float*)d_in[25]; p.he1b = (const float*)d_in[26];
    p.he2W = (const float*)d_in[27]; p.he2b = (const float*)d_in[28];
    p.out  = (float*)d_out;
    gru_kernel<<<NBLK, NTHR>>>(p);
}

// round 4
// speedup vs baseline: 1.4396x; 1.3070x over previous
#include <cuda_runtime.h>

#define NBLK 128
#define NTHR 256
#define B 256
#define TE 300
#define TT 600
#define H 512
#define NIN 128
#define NPV 5
#define EMBD 32
#define NHE 16

typedef unsigned long long ull;

__device__ float g_h0a[B * H], g_h0b[B * H];
__device__ float g_h1a[B * H], g_h1b[B * H];
__device__ float g_z[B * 256];
__device__ float g_pv[B * NPV];
__device__ float g_embs[B * EMBD];
__device__ unsigned g_bar_count;
__device__ unsigned g_bar_sense;

__device__ __forceinline__ void gsync(unsigned& sense) {
    __syncthreads();
    if (threadIdx.x == 0) {
        __threadfence();
        unsigned prev = atomicAdd(&g_bar_count, 1u);
        if (prev == (unsigned)(NBLK - 1)) {
            atomicExch(&g_bar_count, 0u);
            __threadfence();
            *((volatile unsigned*)&g_bar_sense) = sense ^ 1u;
        } else {
            while (*((volatile unsigned*)&g_bar_sense) == sense) __nanosleep(32);
            __threadfence();
        }
    }
    sense ^= 1u;
    __syncthreads();
}

__device__ __forceinline__ void fma2(ull& a, ull x, ull w) {
    asm("fma.rn.f32x2 %0, %1, %2, %0;" : "+l"(a) : "l"(x), "l"(w));
}
__device__ __forceinline__ ull dup2(float w) {
    ull r; unsigned u = __float_as_uint(w);
    asm("mov.b64 %0, {%1,%1};" : "=l"(r) : "r"(u));
    return r;
}
__device__ __forceinline__ float2 u2f(ull v) {
    unsigned lo, hi;
    asm("mov.b64 {%0,%1}, %2;" : "=r"(lo), "=r"(hi) : "l"(v));
    float2 r; r.x = __uint_as_float(lo); r.y = __uint_as_float(hi);
    return r;
}
__device__ __forceinline__ float sigf(float x) { return 1.f / (1.f + __expf(-x)); }

// ---- 3-gate sub-GEMM, 64m x 16j x 3g CTA tile, thread = 4m x 1j x 3g ----
// sW4[k][j] = {w_gate0, w_gate1, w_gate2, pad}: inner loop = 2x LDS.128 + 3 dup + 6 FFMA2.
// Double-buffered smem, 1 __syncthreads per 32-k chunk.
template <int AMODE, int WMODE>
__device__ __forceinline__ void gemm3(
    const float* __restrict__ A, int ldA,
    const float* __restrict__ W, int ldW, int K,
    int m0, int j0, int tm, int tn,
    float* __restrict__ sA, float4* __restrict__ sW, ull (&acc)[2][3]) {
    const int tid = threadIdx.x;
    const int NC = K >> 5;
    float a_r[2][4];
    float w_r[2][3];

    auto ldg = [&](int kb) {
#pragma unroll
        for (int i = 0; i < 2; i++) {
            int f = tid + (i << 8);
            int k = f & 31, mg = f >> 5;      // mg 0..15
            int kk = kb + k;
#pragma unroll
            for (int r = 0; r < 4; r++) {
                int m = m0 + mg * 4 + r;
                if (AMODE == 1 && kk >= 128)
                    a_r[i][r] = g_embs[m * EMBD + (kk - 128)];
                else
                    a_r[i][r] = A[m * ldA + kk];
            }
        }
#pragma unroll
        for (int i = 0; i < 2; i++) {
            int f = tid + (i << 8);
            int k = f & 31, j = (f >> 5) & 15;
            int kk = kb + k;
            (void)WMODE;
#pragma unroll
            for (int g = 0; g < 3; g++)
                w_r[i][g] = W[((g << 9) + j0 + j) * ldW + kk];
        }
    };
    auto st = [&](int pb) {
        float* bA = sA + pb * (32 * 68);
        float4* bW = sW + pb * (32 * 17);
#pragma unroll
        for (int i = 0; i < 2; i++) {
            int f = tid + (i << 8);
            int k = f & 31, mg = f >> 5;
            *(float4*)&bA[k * 68 + mg * 4] =
                make_float4(a_r[i][0], a_r[i][1], a_r[i][2], a_r[i][3]);
        }
#pragma unroll
        for (int i = 0; i < 2; i++) {
            int f = tid + (i << 8);
            int k = f & 31, j = (f >> 5) & 15;
            bW[k * 17 + j] = make_float4(w_r[i][0], w_r[i][1], w_r[i][2], 0.f);
        }
    };
    auto comp = [&](int pb) {
        const float* bA = sA + pb * (32 * 68);
        const float4* bW = sW + pb * (32 * 17);
#pragma unroll 8
        for (int k = 0; k < 32; k++) {
            ulonglong2 av = *(const ulonglong2*)&bA[k * 68 + (tm << 2)];
            float4 w4 = bW[k * 17 + tn];
            ull w0 = dup2(w4.x), w1 = dup2(w4.y), w2 = dup2(w4.z);
            fma2(acc[0][0], av.x, w0); fma2(acc[1][0], av.y, w0);
            fma2(acc[0][1], av.x, w1); fma2(acc[1][1], av.y, w1);
            fma2(acc[0][2], av.x, w2); fma2(acc[1][2], av.y, w2);
        }
    };

    ldg(0);
    st(0);
    if (NC > 1) ldg(32);
    __syncthreads();
    for (int c = 0; c < NC; c++) {
        if (c + 1 < NC) {
            st((c + 1) & 1);
            if (c + 2 < NC) ldg((c + 2) << 5);
        }
        comp(c & 1);
        __syncthreads();
    }
}

template <bool PV>
__device__ __forceinline__ void combine3(
    ull (&aI)[2][3], ull (&aH)[2][3],
    const float* __restrict__ bias, const float* __restrict__ pvw,
    const float* __restrict__ hin, float* __restrict__ hout,
    int m0, int j0, int tm, int tn) {
    int j = j0 + tn;
    float bi0 = bias[tn], bi1 = bias[16 + tn], bi2 = bias[32 + tn];
    float bh0 = bias[48 + tn], bh1 = bias[64 + tn], bh2 = bias[80 + tn];
#pragma unroll
    for (int p = 0; p < 2; p++) {
        float2 vir = u2f(aI[p][0]), viz = u2f(aI[p][1]), vin = u2f(aI[p][2]);
        float2 vhr = u2f(aH[p][0]), vhz = u2f(aH[p][1]), vhn = u2f(aH[p][2]);
#pragma unroll
        for (int u = 0; u < 2; u++) {
            int b = m0 + (tm << 2) + (p << 1) + u;
            float ir = (u ? vir.y : vir.x) + bi0;
            float iz = (u ? viz.y : viz.x) + bi1;
            float in_ = (u ? vin.y : vin.x) + bi2;
            if (PV) {
                const float* pv = &g_pv[b * NPV];
#pragma unroll
                for (int q = 0; q < 5; q++) {
                    float pq = pv[q];
                    ir  += pq * pvw[tn * 5 + q];
                    iz  += pq * pvw[80 + tn * 5 + q];
                    in_ += pq * pvw[160 + tn * 5 + q];
                }
            }
            float hr = (u ? vhr.y : vhr.x) + bh0;
            float hz = (u ? vhz.y : vhz.x) + bh1;
            float hn = (u ? vhn.y : vhn.x) + bh2;
            float r = sigf(ir + hr);
            float z = sigf(iz + hz);
            float n = tanhf(in_ + r * hn);
            hout[b * H + j] = (1.f - z) * n + z * hin[b * H + j];
        }
    }
}

template <int AMODE, int WMODE, bool PV>
__device__ __forceinline__ void gru_step(
    const float* __restrict__ Ain, int ldA,
    const float* __restrict__ Wih, int ldWih, int Kin,
    const float* __restrict__ hin, const float* __restrict__ Whh,
    const float* __restrict__ bias, const float* __restrict__ pvw,
    float* __restrict__ hout,
    int m0, int j0, int tm, int tn, float* sA, float4* sW) {
    ull aI[2][3] = {{0, 0, 0}, {0, 0, 0}};
    ull aH[2][3] = {{0, 0, 0}, {0, 0, 0}};
    gemm3<AMODE, WMODE>(Ain, ldA, Wih, ldWih, Kin, m0, j0, tm, tn, sA, sW, aI);
    gemm3<0, 0>(hin, H, Whh, H, H, m0, j0, tm, tn, sA, sW, aH);
    combine3<PV>(aI, aH, bias, pvw, hin, hout, m0, j0, tm, tn);
}

// heads layer 1: z = relu(d2 @ [fc1|he1]^T + b), 256x256, K=512
__device__ __forceinline__ void heads1(const float* __restrict__ d2,
                                       const float* __restrict__ fc1W, const float* __restrict__ fc1b,
                                       const float* __restrict__ he1W, const float* __restrict__ he1b) {
    __shared__ float As2[32 * 17];
    __shared__ float Ws2[32 * 34];
    int tile = blockIdx.x;
    int m0 = (tile >> 3) * 16;
    int n0 = (tile & 7) * 32;
    int tid = threadIdx.x;
    int m = tid & 15;
    int n2 = (tid >> 4) * 2;

    float acc0 = 0.f, acc1 = 0.f;
    for (int kb = 0; kb < H; kb += 32) {
#pragma unroll
        for (int i = 0; i < 2; i++) {
            int lin = tid + i * NTHR;
            int kk = lin & 31, mm = lin >> 5;
            As2[kk * 17 + mm] = d2[(m0 + mm) * H + kb + kk];
        }
#pragma unroll
        for (int i = 0; i < 4; i++) {
            int lin = tid + i * NTHR;
            int kk = lin & 31, nn = lin >> 5;
            int ng = n0 + nn;
            const float* Wr = (ng < 128) ? (fc1W + ng * H) : (he1W + (ng - 128) * H);
            Ws2[kk * 34 + nn] = Wr[kb + kk];
        }
        __syncthreads();
#pragma unroll
        for (int k = 0; k < 32; k++) {
            float a = As2[k * 17 + m];
            float2 w = *(const float2*)&Ws2[k * 34 + n2];
            acc0 += a * w.x;
            acc1 += a * w.y;
        }
        __syncthreads();
    }
    int b = m0 + m;
    int ng0 = n0 + n2;
    float b0 = (ng0 < 128) ? fc1b[ng0] : he1b[ng0 - 128];
    float b1 = (ng0 + 1 < 128) ? fc1b[ng0 + 1] : he1b[ng0 + 1 - 128];
    g_z[b * 256 + ng0]     = fmaxf(acc0 + b0, 0.f);
    g_z[b * 256 + ng0 + 1] = fmaxf(acc1 + b1, 0.f);
}

__device__ __forceinline__ void heads2(int t,
                                       const float* __restrict__ fc2W, const float* __restrict__ fc2b,
                                       const float* __restrict__ he2W, const float* __restrict__ he2b,
                                       float* __restrict__ out) {
    __shared__ float zs[512];
    int tid = threadIdx.x;
    int b0 = blockIdx.x * 2;
    for (int i = tid; i < 512; i += NTHR) zs[i] = g_z[b0 * 256 + i];
    __syncthreads();
    int warp = tid >> 5, lane = tid & 31;
    for (int d = warp; d < 42; d += 8) {
        int bb = d / 21, o = d % 21;
        const float* wrow;
        int kbase;
        float bias;
        if (o < 5) { wrow = fc2W + o * 128; kbase = 0; bias = fc2b[o]; }
        else       { wrow = he2W + (o - 5) * 128; kbase = 128; bias = he2b[o - 5]; }
        float s = 0.f;
#pragma unroll
        for (int kk = 0; kk < 128; kk += 32)
            s += zs[bb * 256 + kbase + kk + lane] * wrow[kk + lane];
#pragma unroll
        for (int off = 16; off; off >>= 1) s += __shfl_xor_sync(0xffffffffu, s, off);
        if (lane == 0) {
            float v = s + bias;
            int b = b0 + bb;
            if (o < 5) {
                out[b * (TT * NPV) + t * NPV + o] = v;
                g_pv[b * NPV + o] = v;
            } else {
                out[B * TT * NPV + b * (TT * NHE) + t * NHE + (o - 5)] = v;
            }
        }
    }
    __syncthreads();
}

struct P {
    const float *x_cv, *x_cv_target, *pv_init;
    const int* scenario;
    const float* emb;
    const float *eW0i, *eW0h, *eb0i, *eb0h, *eW1i, *eW1h, *eb1i, *eb1h;
    const float *dW0i, *dW0h, *db0i, *db0h, *dW1i, *dW1h, *db1i, *db1h;
    const float *fc1W, *fc1b, *fc2W, *fc2b, *he1W, *he1b, *he2W, *he2b;
    float* out;
};

__global__ void __launch_bounds__(NTHR, 1) gru_kernel(P p) {
    __shared__ __align__(16) float sA[2 * 32 * 68];
    __shared__ __align__(16) float4 sW[2 * 32 * 17];
    __shared__ float sBias[4 * 96];
    __shared__ float sPvw[240];

    unsigned sense = *((volatile unsigned*)&g_bar_sense);
    int tid = threadIdx.x;
    int mt = blockIdx.x >> 5, jt = blockIdx.x & 31;
    int m0 = mt << 6, j0 = jt << 4;
    int tm = tid >> 4, tn = tid & 15;
    int gt = blockIdx.x * NTHR + tid;

    for (int i = gt; i < B * H; i += NBLK * NTHR) { g_h0a[i] = 0.f; g_h1a[i] = 0.f; }
    for (int i = gt; i < B * EMBD; i += NBLK * NTHR)
        g_embs[i] = p.emb[p.scenario[i >> 5] * EMBD + (i & 31)];
    for (int i = gt; i < B * NPV; i += NBLK * NTHR) g_pv[i] = p.pv_init[i];

    {
        const float* bI[4] = { p.eb0i, p.eb1i, p.db0i, p.db1i };
        const float* bH[4] = { p.eb0h, p.eb1h, p.db0h, p.db1h };
        for (int idx = tid; idx < 384; idx += NTHR) {
            int ph = idx / 96, r = idx % 96, g = r >> 4, jj = r & 15;
            sBias[idx] = (g < 3) ? bI[ph][(g << 9) + j0 + jj]
                                 : bH[ph][((g - 3) << 9) + j0 + jj];
        }
        for (int idx = tid; idx < 240; idx += NTHR) {
            int g = idx / 80, r = idx % 80, jj = r / 5, q = r % 5;
            sPvw[idx] = p.dW0i[((g << 9) + j0 + jj) * 133 + 128 + q];
        }
    }
    gsync(sense);

    float* h0buf[2] = { g_h0a, g_h0b };
    float* h1buf[2] = { g_h1a, g_h1b };

    // encoder: 1 grid barrier per step (ping-pong + program order make the rest safe)
    for (int t = 0; t < TE; t++) {
        int rd = t & 1, wr = rd ^ 1;
        gru_step<1, 0, false>(p.x_cv + t * NIN, TE * NIN, p.eW0i, 160, 160,
                              h0buf[rd], p.eW0h, sBias, nullptr,
                              h0buf[wr], m0, j0, tm, tn, sA, sW);
        gsync(sense);
        gru_step<0, 0, false>(h0buf[wr], H, p.eW1i, 512, 512,
                              h1buf[rd], p.eW1h, sBias + 96, nullptr,
                              h1buf[wr], m0, j0, tm, tn, sA, sW);
    }

    // decoder
    for (int t = 0; t < TT; t++) {
        int rd = t & 1, wr = rd ^ 1;
        gru_step<0, 1, true>(p.x_cv_target + t * NIN, TT * NIN, p.dW0i, 133, 128,
                             h0buf[rd], p.dW0h, sBias + 192, sPvw,
                             h0buf[wr], m0, j0, tm, tn, sA, sW);
        gsync(sense);
        gru_step<0, 0, false>(h0buf[wr], H, p.dW1i, 512, 512,
                              h1buf[rd], p.dW1h, sBias + 288, nullptr,
                              h1buf[wr], m0, j0, tm, tn, sA, sW);
        gsync(sense);
        heads1(h1buf[wr], p.fc1W, p.fc1b, p.he1W, p.he1b);
        gsync(sense);
        heads2(t, p.fc2W, p.fc2b, p.he2W, p.he2b, p.out);
        gsync(sense);
    }
}

extern "C" void kernel_launch(void* const* d_in, const int* in_sizes, int n_in,
                              void* d_out, int out_size) {
    (void)in_sizes; (void)n_in; (void)out_size;
    P p;
    p.x_cv        = (const float*)d_in[0];
    p.x_cv_target = (const float*)d_in[1];
    p.pv_init     = (const float*)d_in[2];
    p.scenario    = (const int*)d_in[3];
    p.emb         = (const float*)d_in[4];
    p.eW0i = (const float*)d_in[5];  p.eW0h = (const float*)d_in[6];
    p.eb0i = (const float*)d_in[7];  p.eb0h = (const float*)d_in[8];
    p.eW1i = (const float*)d_in[9];  p.eW1h = (const float*)d_in[10];
    p.eb1i = (const float*)d_in[11]; p.eb1h = (const float*)d_in[12];
    p.dW0i = (const float*)d_in[13]; p.dW0h = (const float*)d_in[14];
    p.db0i = (const float*)d_in[15]; p.db0h = (const float*)d_in[16];
    p.dW1i = (const float*)d_in[17]; p.dW1h = (const float*)d_in[18];
    p.db1i = (const float*)d_in[19]; p.db1h = (const float*)d_in[20];
    p.fc1W = (const float*)d_in[21]; p.fc1b = (const float*)d_in[22];
    p.fc2W = (const float*)d_in[23]; p.fc2b = (const float*)d_in[24];
    p.he1W = (const float*)d_in[25]; p.he1b = (const float*)d_in[26];
    p.he2W = (const float*)d_in[27]; p.he2b = (const float*)d_in[28];
    p.out  = (float*)d_out;
    gru_kernel<<<NBLK, NTHR>>>(p);
}